// round 14
// baseline (speedup 1.0000x reference)
#include <cuda_runtime.h>
#include <cstdint>

typedef unsigned long long u64;

// ---------------- device scratch (no allocations allowed) ----------------
__device__ float g_part_edge[160][64];
__device__ float g_part_node[160][64];
__device__ float g_zhist[64];
__device__ float g_base[64];
__device__ float g_av[64];
__device__ float g_bv[64];
__device__ float g_w2v[64];

// ---------------- f32x2 packed helpers ------------------------------------
__device__ __forceinline__ u64 pk2(float a, float b) {
    u64 r; asm("mov.b64 %0,{%1,%2};" : "=l"(r) : "f"(a), "f"(b)); return r;
}
__device__ __forceinline__ void up2(u64 v, float& a, float& b) {
    asm("mov.b64 {%0,%1},%2;" : "=f"(a), "=f"(b) : "l"(v));
}
__device__ __forceinline__ u64 f2fma(u64 a, u64 b, u64 c) {
    u64 d; asm("fma.rn.f32x2 %0,%1,%2,%3;" : "=l"(d) : "l"(a), "l"(b), "l"(c)); return d;
}
__device__ __forceinline__ u64 add2(u64 a, u64 b) {
    u64 d; asm("add.rn.f32x2 %0,%1,%2;" : "=l"(d) : "l"(a), "l"(b)); return d;
}
__device__ __forceinline__ u64 relu2(u64 v) {
    u64 r;
    asm("{\n\t.reg .f32 l,h;\n\t"
        "mov.b64 {l,h}, %1;\n\t"
        "max.f32 l, l, 0f00000000;\n\t"
        "max.f32 h, h, 0f00000000;\n\t"
        "mov.b64 %0, {l,h};\n\t}"
        : "=l"(r) : "l"(v));
    return r;
}
__device__ __forceinline__ float tanh_ap(float x) {
    float r; asm("tanh.approx.f32 %0,%1;" : "=f"(r) : "f"(x)); return r;
}
__device__ __forceinline__ float sigm(float x) { return 1.f / (1.f + __expf(-x)); }

#define PNTH  768
#define NWP   24                // warps per block
#define RPS2  1536              // rows per stage
#define NIT   (RPS2 / 2 / NWP)  // 32 compute iterations (768 row-pairs / 24 warps)
#define KPF   1544              // padded float stride per input-feature column
#define REDW2 66

// ---------------- staged MLP mean-pool reduction (6 warps/SMSP) -----------
// 768 threads. lane = output pair (j0 = 2*lane), warp = row-slice (24 warps).
// f32x2 lanes = (row 2rp, row 2rp+1); all 32 lanes of a warp read the SAME
// shared address -> broadcast LDS.64. Staging is COALESCED float2 loads from
// gmem, scattered into transposed shared (sht[k][row]).
template<int INF>
__device__ __forceinline__ void phase(const float* __restrict__ X,
                                      const float* __restrict__ W,
                                      const float* __restrict__ bias,
                                      int nrows, float* __restrict__ partial,
                                      int nb, int b,
                                      float* __restrict__ sht,  // INF*KPF floats
                                      float* __restrict__ red)  // 24*REDW2 floats
{
    const int tid  = threadIdx.x;
    const int lane = tid & 31;
    const int w    = tid >> 5;        // warp 0..23
    const int j0   = lane * 2;

    u64 w2[INF * 2];
    u64 b2[2];
#pragma unroll
    for (int k = 0; k < INF; k++) {
        const float wa = W[k * 64 + j0];
        const float wb = W[k * 64 + j0 + 1];
        w2[k * 2]     = pk2(wa, wa);
        w2[k * 2 + 1] = pk2(wb, wb);
    }
    {
        const float ba = bias[j0], bb = bias[j0 + 1];
        b2[0] = pk2(ba, ba);
        b2[1] = pk2(bb, bb);
    }
    u64 acc0 = 0ull, acc1 = 0ull;

    const int nstages = (nrows + RPS2 - 1) / RPS2;
    const int nelem = nrows * INF;
    constexpr int NF2 = (RPS2 * INF) / (2 * PNTH);  // float2 per thread (5 or 2)
    float2 rg[NF2];

    // prefetch first stage (coalesced float2)
    if (b < nstages) {
        const int e2base = b * (RPS2 * INF / 2);
#pragma unroll
        for (int t = 0; t < NF2; t++) {
            const int e = (e2base + tid + t * PNTH) * 2;
            float2 v;
            v.x = (e     < nelem) ? X[e]     : 0.f;
            v.y = (e + 1 < nelem) ? X[e + 1] : 0.f;
            rg[t] = v;
        }
    }

    for (int s = b; s < nstages; s += nb) {
        __syncthreads();
        // scatter into transposed shared: element e -> sht[(e%INF)*KPF + e/INF]
#pragma unroll
        for (int t = 0; t < NF2; t++) {
            const int e = (tid + t * PNTH) * 2;     // local element in stage
            const int r0 = e / INF, k0 = e - r0 * INF;
            sht[k0 * KPF + r0] = rg[t].x;
            const int e1 = e + 1;
            const int r1 = e1 / INF, k1 = e1 - r1 * INF;
            sht[k1 * KPF + r1] = rg[t].y;
        }
        __syncthreads();

        // prefetch next stage (overlaps compute)
        const int sn = s + nb;
        if (sn < nstages) {
            const int e2base = sn * (RPS2 * INF / 2);
#pragma unroll
            for (int t = 0; t < NF2; t++) {
                const int e = (e2base + tid + t * PNTH) * 2;
                float2 v;
                v.x = (e     < nelem) ? X[e]     : 0.f;
                v.y = (e + 1 < nelem) ? X[e + 1] : 0.f;
                rg[t] = v;
            }
        }

        const int rows = min(RPS2, nrows - s * RPS2);
        if (rows == RPS2) {
#pragma unroll 4
            for (int it = 0; it < NIT; ++it) {       // 32 iters x 24 warps = 768 rp
                const int rp = it * NWP + w;
                u64 x2[INF];
#pragma unroll
                for (int k = 0; k < INF; k++)
                    x2[k] = ((const u64*)(sht + k * KPF))[rp];
                u64 y0 = b2[0], y1 = b2[1];
#pragma unroll
                for (int k = 0; k < INF; k++) {
                    y0 = f2fma(x2[k], w2[k * 2],     y0);
                    y1 = f2fma(x2[k], w2[k * 2 + 1], y1);
                }
                acc0 = add2(relu2(y0), acc0);
                acc1 = add2(relu2(y1), acc1);
            }
        } else {
#pragma unroll 4
            for (int it = 0; it < NIT; ++it) {
                const int rp = it * NWP + w;
                const float m0 = (2 * rp < rows) ? 1.f : 0.f;
                const float m1 = (2 * rp + 1 < rows) ? 1.f : 0.f;
                const u64 mask = pk2(m0, m1);
                u64 x2[INF];
#pragma unroll
                for (int k = 0; k < INF; k++)
                    x2[k] = ((const u64*)(sht + k * KPF))[rp];
                u64 y0 = b2[0], y1 = b2[1];
#pragma unroll
                for (int k = 0; k < INF; k++) {
                    y0 = f2fma(x2[k], w2[k * 2],     y0);
                    y1 = f2fma(x2[k], w2[k * 2 + 1], y1);
                }
                acc0 = f2fma(relu2(y0), mask, acc0);
                acc1 = f2fma(relu2(y1), mask, acc1);
            }
        }
    }

    // deterministic cross-warp reduce: 24 warps x 64 outputs
    __syncthreads();
    {
        float a, bb;
        up2(acc0, a, bb); red[w * REDW2 + j0]     = a + bb;
        up2(acc1, a, bb); red[w * REDW2 + j0 + 1] = a + bb;
    }
    __syncthreads();
    if (tid < 64) {
        float sum = 0.f;
#pragma unroll 8
        for (int r2 = 0; r2 < NWP; r2++) sum += red[r2 * REDW2 + tid];
        partial[tid] = sum;
    }
    __syncthreads();
}

// ---------------- kernel 1: LSTM (block 0) + node/edge reduce -------------
__global__ void __launch_bounds__(PNTH, 1) k1(
    const float* __restrict__ node, const float* __restrict__ edge,
    const float* __restrict__ hist, int Nn, int Ne, int T,
    const float* __restrict__ nodeW, const float* __restrict__ nodeb,
    const float* __restrict__ edgeW, const float* __restrict__ edgeb,
    const float* __restrict__ Wih, const float* __restrict__ Whh,
    const float* __restrict__ bih, const float* __restrict__ bhh)
{
    __shared__ __align__(16) float sht[5 * KPF];        // 30880 B
    __shared__ __align__(16) float red[NWP * REDW2];    //  6336 B
    __shared__ float sh_hist[608];
    __shared__ float sh_g[256];
    __shared__ __align__(8) float sh_h[64];

    const int tid = threadIdx.x;

    if (blockIdx.x == 0) {
        // ---------------- LSTM: 256 gate threads (of 768) -----------------
        u64 w2[32];
        float wi0 = 0.f, wi1 = 0.f, wi2 = 0.f, bsum = 0.f;
        if (tid < 256) {
            const float2* wr = (const float2*)(Whh + tid * 64);
#pragma unroll
            for (int k = 0; k < 32; k++) { float2 p = wr[k]; w2[k] = pk2(p.x, p.y); }
            wi0 = Wih[tid * 3]; wi1 = Wih[tid * 3 + 1]; wi2 = Wih[tid * 3 + 2];
            bsum = bih[tid] + bhh[tid];
        }
        const bool hsh = (T * 3 <= 608);
        for (int i = tid; i < T * 3 && i < 608; i += PNTH) sh_hist[i] = hist[i];
        if (tid < 64) sh_h[tid] = 0.f;
        float c = 0.f;
        __syncthreads();

        const bool is_tanh_gate = (tid >= 128 && tid < 192);
        for (int t = 0; t < T; t++) {
            if (tid < 256) {
                const float* xp = hsh ? (sh_hist + t * 3) : (hist + t * 3);
                float pre = fmaf(wi0, xp[0], fmaf(wi1, xp[1], fmaf(wi2, xp[2], bsum)));
                const u64* hp = (const u64*)sh_h;
                u64 a0 = 0, a1 = 0, a2 = 0, a3 = 0;
#pragma unroll
                for (int k = 0; k < 32; k += 4) {
                    a0 = f2fma(w2[k],     hp[k],     a0);
                    a1 = f2fma(w2[k + 1], hp[k + 1], a1);
                    a2 = f2fma(w2[k + 2], hp[k + 2], a2);
                    a3 = f2fma(w2[k + 3], hp[k + 3], a3);
                }
                float s0, s1, s2, s3, s4, s5, s6, s7;
                up2(a0, s0, s1); up2(a1, s2, s3); up2(a2, s4, s5); up2(a3, s6, s7);
                const float z = pre + ((s0 + s1) + (s2 + s3)) + ((s4 + s5) + (s6 + s7));
                sh_g[tid] = is_tanh_gate ? tanh_ap(z) : sigm(z);
            }
            __syncthreads();
            if (tid < 64) {
                const float ig = sh_g[tid], fg = sh_g[64 + tid];
                const float gg = sh_g[128 + tid], og = sh_g[192 + tid];
                c = fmaf(fg, c, ig * gg);
                sh_h[tid] = og * tanh_ap(c);
            }
            __syncthreads();
        }
        if (tid < 64) g_zhist[tid] = sh_h[tid];
    } else {
        const int b = blockIdx.x - 1;
        const int nb = gridDim.x - 1;
        phase<2>(node, nodeW, nodeb, Nn, g_part_node[b], nb, b, sht, red);
        phase<5>(edge, edgeW, edgeb, Ne, g_part_edge[b], nb, b, sht, red);
    }
}

// ---------------- kernel 2: finalize ctx + precompute base/a/b/w2 ---------
#define NB 147

__global__ void __launch_bounds__(512) k2(int Nn, int Ne,
                   const float* __restrict__ W1, const float* __restrict__ b1,
                   const float* __restrict__ W2f)
{
    __shared__ float ctx[192];
    __shared__ float t1[512], t2[512];
    const int tid = threadIdx.x;
    const int c = tid >> 6, j = tid & 63;   // 8 groups of 64

    float se = 0.f, sn = 0.f;
#pragma unroll
    for (int i = 0; i < 19; i++) {          // ceil(147/8)=19, guarded
        const int b = c + i * 8;
        if (b < NB) {
            se += g_part_edge[b][j];
            sn += g_part_node[b][j];
        }
    }
    t1[tid] = se; t2[tid] = sn;
    __syncthreads();
    if (tid < 64) {
        float e = 0.f, n = 0.f;
#pragma unroll
        for (int g = 0; g < 8; g++) { e += t1[g * 64 + tid]; n += t2[g * 64 + tid]; }
        ctx[tid]       = n * (1.f / (float)Nn);
        ctx[64 + tid]  = e * (1.f / (float)Ne);
        ctx[128 + tid] = g_zhist[tid];
    }
    __syncthreads();
    float p = 0.f;
    const int i0 = c * 24;
#pragma unroll
    for (int i = 0; i < 24; i++) p = fmaf(ctx[i0 + i], W1[(i0 + i) * 64 + j], p);
    __syncthreads();
    t1[tid] = p;
    __syncthreads();
    if (tid < 64) {
        float s = b1[tid];
#pragma unroll
        for (int g = 0; g < 8; g++) s += t1[g * 64 + tid];
        g_base[tid] = s;
        g_av[tid]   = W1[192 * 64 + tid];
        g_bv[tid]   = W1[193 * 64 + tid];
        g_w2v[tid]  = W2f[tid];
    }
}

// ---------------- kernel 3: candidate scoring (ILP=8, R2-measured) --------
__global__ void __launch_bounds__(256) k3(const int* __restrict__ cand, int P,
                                          const int* __restrict__ Np,
                                          const float* __restrict__ fb2,
                                          float* __restrict__ out)
{
    __shared__ __align__(16) u64 s4[128];   // [jp]{base2, a2, b2, w22}
    const int tid = threadIdx.x;
    if (tid < 32) {
        s4[tid * 4 + 0] = pk2(g_base[2 * tid], g_base[2 * tid + 1]);
        s4[tid * 4 + 1] = pk2(g_av[2 * tid],   g_av[2 * tid + 1]);
        s4[tid * 4 + 2] = pk2(g_bv[2 * tid],   g_bv[2 * tid + 1]);
        s4[tid * 4 + 3] = pk2(g_w2v[2 * tid],  g_w2v[2 * tid + 1]);
    }
    const float invd = 1.f / ((float)(*Np) - 1.f + 1e-9f);
    const float bias2 = fb2[0];
    __syncthreads();

    const int p0 = blockIdx.x * 2048 + tid;
    u64 cx2[8], cy2[8];
#pragma unroll
    for (int i = 0; i < 8; i++) {
        const int p = p0 + i * 256;
        float cx = 0.f, cy = 0.f;
        if (p < P) {
            const int2 cp = ((const int2*)cand)[p];
            cx = (float)cp.x * invd;
            cy = (float)cp.y * invd;
        }
        cx2[i] = pk2(cx, cx);
        cy2[i] = pk2(cy, cy);
    }

    u64 acc[8] = {0, 0, 0, 0, 0, 0, 0, 0};
#pragma unroll 8
    for (int jp = 0; jp < 32; jp++) {
        const u64 bb = s4[jp * 4 + 0];
        const u64 aa = s4[jp * 4 + 1];
        const u64 bv = s4[jp * 4 + 2];
        const u64 ww = s4[jp * 4 + 3];
#pragma unroll
        for (int i = 0; i < 8; i++) {
            u64 tt = f2fma(cx2[i], aa, bb);
            tt = f2fma(cy2[i], bv, tt);
            acc[i] = f2fma(relu2(tt), ww, acc[i]);
        }
    }
#pragma unroll
    for (int i = 0; i < 8; i++) {
        const int p = p0 + i * 256;
        if (p < P) {
            float l, h; up2(acc[i], l, h);
            out[p] = l + h + bias2;
        }
    }
}

// ---------------- launch ---------------------------------------------------
extern "C" void kernel_launch(void* const* d_in, const int* in_sizes, int n_in,
                              void* d_out, int out_size)
{
    const float* node  = (const float*)d_in[0];
    const float* edge  = (const float*)d_in[1];
    const float* hist  = (const float*)d_in[2];
    const int*   cand  = (const int*)d_in[3];
    const int*   Np    = (const int*)d_in[4];
    const float* nodeW = (const float*)d_in[5];
    const float* nodeb = (const float*)d_in[6];
    const float* edgeW = (const float*)d_in[7];
    const float* edgeb = (const float*)d_in[8];
    const float* Wih   = (const float*)d_in[9];
    const float* Whh   = (const float*)d_in[10];
    const float* bih   = (const float*)d_in[11];
    const float* bhh   = (const float*)d_in[12];
    const float* fW1   = (const float*)d_in[13];
    const float* fb1   = (const float*)d_in[14];
    const float* fW2   = (const float*)d_in[15];
    const float* fb2   = (const float*)d_in[16];

    const int Nn = in_sizes[0] / 2;
    const int Ne = in_sizes[1] / 5;
    const int T  = in_sizes[2] / 3;
    const int P  = in_sizes[3] / 2;

    const int GRID1 = 148;  // block 0 = LSTM, 147 = node/edge reduce (== NB)
    k1<<<GRID1, PNTH>>>(node, edge, hist, Nn, Ne, T,
                        nodeW, nodeb, edgeW, edgeb, Wih, Whh, bih, bhh);
    k2<<<1, 512>>>(Nn, Ne, fW1, fb1, fW2);
    const int g3 = (P + 2047) / 2048;
    k3<<<g3, 256>>>(cand, P, Np, fb2, (float*)d_out);
}

// round 15
// speedup vs baseline: 1.2142x; 1.2142x over previous
#include <cuda_runtime.h>
#include <cstdint>

typedef unsigned long long u64;

// ---------------- device scratch (no allocations allowed) ----------------
__device__ float g_part_edge[320][64];
__device__ float g_part_node[320][64];
__device__ float g_zhist[64];
__device__ float g_base[64];
__device__ float g_av[64];
__device__ float g_bv[64];
__device__ float g_w2v[64];

// ---------------- f32x2 packed helpers ------------------------------------
__device__ __forceinline__ u64 pk2(float a, float b) {
    u64 r; asm("mov.b64 %0,{%1,%2};" : "=l"(r) : "f"(a), "f"(b)); return r;
}
__device__ __forceinline__ void up2(u64 v, float& a, float& b) {
    asm("mov.b64 {%0,%1},%2;" : "=f"(a), "=f"(b) : "l"(v));
}
__device__ __forceinline__ u64 f2fma(u64 a, u64 b, u64 c) {
    u64 d; asm("fma.rn.f32x2 %0,%1,%2,%3;" : "=l"(d) : "l"(a), "l"(b), "l"(c)); return d;
}
__device__ __forceinline__ u64 add2(u64 a, u64 b) {
    u64 d; asm("add.rn.f32x2 %0,%1,%2;" : "=l"(d) : "l"(a), "l"(b)); return d;
}
__device__ __forceinline__ u64 relu2(u64 v) {
    u64 r;
    asm("{\n\t.reg .f32 l,h;\n\t"
        "mov.b64 {l,h}, %1;\n\t"
        "max.f32 l, l, 0f00000000;\n\t"
        "max.f32 h, h, 0f00000000;\n\t"
        "mov.b64 %0, {l,h};\n\t}"
        : "=l"(r) : "l"(v));
    return r;
}
__device__ __forceinline__ float tanh_ap(float x) {
    float r; asm("tanh.approx.f32 %0,%1;" : "=f"(r) : "f"(x)); return r;
}
__device__ __forceinline__ float sigm(float x) { return 1.f / (1.f + __expf(-x)); }

// ---------------- staged MLP mean-pool reduction --------------------------
// R12's proven phase, halved to 256 threads / 512-row stages so TWO CTAs fit
// per SM (independent barrier domains overlap each other's stalls).
// group of 16 threads (tid&15) -> 4 outputs each; f32x2 lanes = (rowA,rowB);
// shared TRANSPOSED: sht[k][row] -> lane pair is one natural LDS.64.
#define NTH2  256
#define RPS   512
#define KPAD  520               // padded float stride (even -> u64 stride 260)

template<int INF>
__device__ __forceinline__ void phase(const float* __restrict__ X,
                                      const float* __restrict__ W,
                                      const float* __restrict__ bias,
                                      int nrows, float* __restrict__ partial,
                                      int nb, int b,
                                      float* __restrict__ sht,  // INF*KPAD floats
                                      float* __restrict__ red)  // 1024 floats
{
    const int tid = threadIdx.x;
    const int j0 = (tid & 15) * 4;
    const int rpb = tid >> 4;          // row-slice 0..15

    u64 w2[INF * 4];
    u64 b2[4];
#pragma unroll
    for (int k = 0; k < INF; k++)
#pragma unroll
        for (int jj = 0; jj < 4; jj++) {
            float w = W[k * 64 + j0 + jj];
            w2[k * 4 + jj] = pk2(w, w);
        }
#pragma unroll
    for (int jj = 0; jj < 4; jj++) {
        float bb = bias[j0 + jj];
        b2[jj] = pk2(bb, bb);
    }

    u64 acc[4] = {0ull, 0ull, 0ull, 0ull};

    const int nstages = (nrows + RPS - 1) / RPS;
    float rg[2][INF];

    // prefetch first stage
    if (b < nstages) {
        const int r0 = b * RPS;
#pragma unroll
        for (int t2 = 0; t2 < 2; t2++) {
            const int gr = r0 + tid + t2 * NTH2;
            if (gr < nrows) {
#pragma unroll
                for (int k = 0; k < INF; k++) rg[t2][k] = X[gr * INF + k];
            } else {
#pragma unroll
                for (int k = 0; k < INF; k++) rg[t2][k] = 0.f;
            }
        }
    }

    for (int s = b; s < nstages; s += nb) {
        __syncthreads();
#pragma unroll
        for (int t2 = 0; t2 < 2; t2++) {
            const int j = tid + t2 * NTH2;
#pragma unroll
            for (int k = 0; k < INF; k++) sht[k * KPAD + j] = rg[t2][k];
        }
        __syncthreads();

        // prefetch next stage (overlaps compute)
        const int sn = s + nb;
        if (sn < nstages) {
            const int r0 = sn * RPS;
#pragma unroll
            for (int t2 = 0; t2 < 2; t2++) {
                const int gr = r0 + tid + t2 * NTH2;
                if (gr < nrows) {
#pragma unroll
                    for (int k = 0; k < INF; k++) rg[t2][k] = X[gr * INF + k];
                } else {
#pragma unroll
                    for (int k = 0; k < INF; k++) rg[t2][k] = 0.f;
                }
            }
        }

        const int rows = min(RPS, nrows - s * RPS);
        if (rows == RPS) {
#pragma unroll 4
            for (int it = 0; it < RPS / 32; ++it) {    // 16 iters x 16 slices
                const int rp = it * 16 + rpb;
                u64 x2[INF];
#pragma unroll
                for (int k = 0; k < INF; k++)
                    x2[k] = ((const u64*)(sht + k * KPAD))[rp];
#pragma unroll
                for (int jj = 0; jj < 4; jj++) {
                    u64 y = b2[jj];
#pragma unroll
                    for (int k = 0; k < INF; k++)
                        y = f2fma(x2[k], w2[k * 4 + jj], y);
                    acc[jj] = add2(relu2(y), acc[jj]);
                }
            }
        } else {
#pragma unroll 4
            for (int it = 0; it < RPS / 32; ++it) {
                const int rp = it * 16 + rpb;
                const float m0 = (2 * rp < rows) ? 1.f : 0.f;
                const float m1 = (2 * rp + 1 < rows) ? 1.f : 0.f;
                const u64 mask = pk2(m0, m1);
                u64 x2[INF];
#pragma unroll
                for (int k = 0; k < INF; k++)
                    x2[k] = ((const u64*)(sht + k * KPAD))[rp];
#pragma unroll
                for (int jj = 0; jj < 4; jj++) {
                    u64 y = b2[jj];
#pragma unroll
                    for (int k = 0; k < INF; k++)
                        y = f2fma(x2[k], w2[k * 4 + jj], y);
                    acc[jj] = f2fma(relu2(y), mask, acc[jj]);
                }
            }
        }
    }

    // deterministic cross-thread reduce
    __syncthreads();
    {
        float4 v;
        float a, bb;
        up2(acc[0], a, bb); v.x = a + bb;
        up2(acc[1], a, bb); v.y = a + bb;
        up2(acc[2], a, bb); v.z = a + bb;
        up2(acc[3], a, bb); v.w = a + bb;
        ((float4*)red)[tid] = v;
    }
    __syncthreads();
    if (tid < 64) {
        float s = 0.f;
#pragma unroll 8
        for (int rp = 0; rp < 16; rp++) s += red[rp * 64 + tid];
        partial[tid] = s;
    }
    __syncthreads();
}

// ---------------- kernel 1: LSTM (block 0) + node/edge reduce -------------
// 256 threads/block, 2 CTAs per SM (independent barrier domains).
__global__ void __launch_bounds__(NTH2, 2) k1(
    const float* __restrict__ node, const float* __restrict__ edge,
    const float* __restrict__ hist, int Nn, int Ne, int T,
    const float* __restrict__ nodeW, const float* __restrict__ nodeb,
    const float* __restrict__ edgeW, const float* __restrict__ edgeb,
    const float* __restrict__ Wih, const float* __restrict__ Whh,
    const float* __restrict__ bih, const float* __restrict__ bhh)
{
    __shared__ __align__(16) float sht[5 * KPAD];   // 10400 B
    __shared__ __align__(16) float red[1024];       //  4096 B
    __shared__ float sh_hist[608];
    __shared__ float sh_g[256];
    __shared__ __align__(8) float sh_h[64];

    const int tid = threadIdx.x;

    if (blockIdx.x == 0) {
        // ------- LSTM: 256 threads = one gate row each (R1-proven) --------
        u64 w2[32];
        const float2* wr = (const float2*)(Whh + tid * 64);
#pragma unroll
        for (int k = 0; k < 32; k++) { float2 p = wr[k]; w2[k] = pk2(p.x, p.y); }
        const float wi0 = Wih[tid * 3], wi1 = Wih[tid * 3 + 1], wi2 = Wih[tid * 3 + 2];
        const float bsum = bih[tid] + bhh[tid];

        const bool hsh = (T * 3 <= 608);
        for (int i = tid; i < T * 3 && i < 608; i += NTH2) sh_hist[i] = hist[i];
        if (tid < 64) sh_h[tid] = 0.f;
        float c = 0.f;
        __syncthreads();

        const bool is_tanh_gate = (tid >= 128 && tid < 192);
        for (int t = 0; t < T; t++) {
            const float* xp = hsh ? (sh_hist + t * 3) : (hist + t * 3);
            float pre = fmaf(wi0, xp[0], fmaf(wi1, xp[1], fmaf(wi2, xp[2], bsum)));
            const u64* hp = (const u64*)sh_h;
            u64 a0 = 0, a1 = 0, a2 = 0, a3 = 0;
#pragma unroll
            for (int k = 0; k < 32; k += 4) {
                a0 = f2fma(w2[k],     hp[k],     a0);
                a1 = f2fma(w2[k + 1], hp[k + 1], a1);
                a2 = f2fma(w2[k + 2], hp[k + 2], a2);
                a3 = f2fma(w2[k + 3], hp[k + 3], a3);
            }
            float s0, s1, s2, s3, s4, s5, s6, s7;
            up2(a0, s0, s1); up2(a1, s2, s3); up2(a2, s4, s5); up2(a3, s6, s7);
            const float z = pre + ((s0 + s1) + (s2 + s3)) + ((s4 + s5) + (s6 + s7));
            sh_g[tid] = is_tanh_gate ? tanh_ap(z) : sigm(z);
            __syncthreads();
            if (tid < 64) {
                const float ig = sh_g[tid], fg = sh_g[64 + tid];
                const float gg = sh_g[128 + tid], og = sh_g[192 + tid];
                c = fmaf(fg, c, ig * gg);
                sh_h[tid] = og * tanh_ap(c);
            }
            __syncthreads();
        }
        if (tid < 64) g_zhist[tid] = sh_h[tid];
    } else {
        const int b = blockIdx.x - 1;
        const int nb = gridDim.x - 1;
        phase<2>(node, nodeW, nodeb, Nn, g_part_node[b], nb, b, sht, red);
        phase<5>(edge, edgeW, edgeb, Ne, g_part_edge[b], nb, b, sht, red);
    }
}

// ---------------- kernel 2: finalize ctx + precompute base/a/b/w2 ---------
#define NB 294

__global__ void __launch_bounds__(512) k2(int Nn, int Ne,
                   const float* __restrict__ W1, const float* __restrict__ b1,
                   const float* __restrict__ W2f)
{
    __shared__ float ctx[192];
    __shared__ float t1[512], t2[512];
    const int tid = threadIdx.x;
    const int c = tid >> 6, j = tid & 63;   // 8 groups of 64

    float se = 0.f, sn = 0.f;
#pragma unroll
    for (int i = 0; i < 37; i++) {          // ceil(294/8)=37, guarded
        const int b = c + i * 8;
        if (b < NB) {
            se += g_part_edge[b][j];
            sn += g_part_node[b][j];
        }
    }
    t1[tid] = se; t2[tid] = sn;
    __syncthreads();
    if (tid < 64) {
        float e = 0.f, n = 0.f;
#pragma unroll
        for (int g = 0; g < 8; g++) { e += t1[g * 64 + tid]; n += t2[g * 64 + tid]; }
        ctx[tid]       = n * (1.f / (float)Nn);
        ctx[64 + tid]  = e * (1.f / (float)Ne);
        ctx[128 + tid] = g_zhist[tid];
    }
    __syncthreads();
    float p = 0.f;
    const int i0 = c * 24;
#pragma unroll
    for (int i = 0; i < 24; i++) p = fmaf(ctx[i0 + i], W1[(i0 + i) * 64 + j], p);
    __syncthreads();
    t1[tid] = p;
    __syncthreads();
    if (tid < 64) {
        float s = b1[tid];
#pragma unroll
        for (int g = 0; g < 8; g++) s += t1[g * 64 + tid];
        g_base[tid] = s;
        g_av[tid]   = W1[192 * 64 + tid];
        g_bv[tid]   = W1[193 * 64 + tid];
        g_w2v[tid]  = W2f[tid];
    }
}

// ---------------- kernel 3: candidate scoring (ILP=8, measured-best) ------
__global__ void __launch_bounds__(256) k3(const int* __restrict__ cand, int P,
                                          const int* __restrict__ Np,
                                          const float* __restrict__ fb2,
                                          float* __restrict__ out)
{
    __shared__ __align__(16) u64 s4[128];   // [jp]{base2, a2, b2, w22}
    const int tid = threadIdx.x;
    if (tid < 32) {
        s4[tid * 4 + 0] = pk2(g_base[2 * tid], g_base[2 * tid + 1]);
        s4[tid * 4 + 1] = pk2(g_av[2 * tid],   g_av[2 * tid + 1]);
        s4[tid * 4 + 2] = pk2(g_bv[2 * tid],   g_bv[2 * tid + 1]);
        s4[tid * 4 + 3] = pk2(g_w2v[2 * tid],  g_w2v[2 * tid + 1]);
    }
    const float invd = 1.f / ((float)(*Np) - 1.f + 1e-9f);
    const float bias2 = fb2[0];
    __syncthreads();

    const int p0 = blockIdx.x * 2048 + tid;
    u64 cx2[8], cy2[8];
#pragma unroll
    for (int i = 0; i < 8; i++) {
        const int p = p0 + i * 256;
        float cx = 0.f, cy = 0.f;
        if (p < P) {
            const int2 cp = ((const int2*)cand)[p];
            cx = (float)cp.x * invd;
            cy = (float)cp.y * invd;
        }
        cx2[i] = pk2(cx, cx);
        cy2[i] = pk2(cy, cy);
    }

    u64 acc[8] = {0, 0, 0, 0, 0, 0, 0, 0};
#pragma unroll 8
    for (int jp = 0; jp < 32; jp++) {
        const u64 bb = s4[jp * 4 + 0];
        const u64 aa = s4[jp * 4 + 1];
        const u64 bv = s4[jp * 4 + 2];
        const u64 ww = s4[jp * 4 + 3];
#pragma unroll
        for (int i = 0; i < 8; i++) {
            u64 tt = f2fma(cx2[i], aa, bb);
            tt = f2fma(cy2[i], bv, tt);
            acc[i] = f2fma(relu2(tt), ww, acc[i]);
        }
    }
#pragma unroll
    for (int i = 0; i < 8; i++) {
        const int p = p0 + i * 256;
        if (p < P) {
            float l, h; up2(acc[i], l, h);
            out[p] = l + h + bias2;
        }
    }
}

// ---------------- launch ---------------------------------------------------
extern "C" void kernel_launch(void* const* d_in, const int* in_sizes, int n_in,
                              void* d_out, int out_size)
{
    const float* node  = (const float*)d_in[0];
    const float* edge  = (const float*)d_in[1];
    const float* hist  = (const float*)d_in[2];
    const int*   cand  = (const int*)d_in[3];
    const int*   Np    = (const int*)d_in[4];
    const float* nodeW = (const float*)d_in[5];
    const float* nodeb = (const float*)d_in[6];
    const float* edgeW = (const float*)d_in[7];
    const float* edgeb = (const float*)d_in[8];
    const float* Wih   = (const float*)d_in[9];
    const float* Whh   = (const float*)d_in[10];
    const float* bih   = (const float*)d_in[11];
    const float* bhh   = (const float*)d_in[12];
    const float* fW1   = (const float*)d_in[13];
    const float* fb1   = (const float*)d_in[14];
    const float* fW2   = (const float*)d_in[15];
    const float* fb2   = (const float*)d_in[16];

    const int Nn = in_sizes[0] / 2;
    const int Ne = in_sizes[1] / 5;
    const int T  = in_sizes[2] / 3;
    const int P  = in_sizes[3] / 2;

    const int GRID1 = NB + 1;   // block 0 = LSTM, 294 phase blocks (2 CTAs/SM)
    k1<<<GRID1, NTH2>>>(node, edge, hist, Nn, Ne, T,
                        nodeW, nodeb, edgeW, edgeb, Wih, Whh, bih, bhh);
    k2<<<1, 512>>>(Nn, Ne, fW1, fb1, fW2);
    const int g3 = (P + 2047) / 2048;
    k3<<<g3, 256>>>(cand, P, Np, fb2, (float*)d_out);
}

// round 16
// speedup vs baseline: 1.2400x; 1.0212x over previous
#include <cuda_runtime.h>
#include <cstdint>

typedef unsigned long long u64;

// ---------------- device scratch (no allocations allowed) ----------------
__device__ float g_part_edge[160][64];
__device__ float g_part_node[160][64];
__device__ float g_zhist[64];
__device__ float g_base[64];
__device__ float g_av[64];
__device__ float g_bv[64];
__device__ float g_w2v[64];

// ---------------- f32x2 packed helpers ------------------------------------
__device__ __forceinline__ u64 pk2(float a, float b) {
    u64 r; asm("mov.b64 %0,{%1,%2};" : "=l"(r) : "f"(a), "f"(b)); return r;
}
__device__ __forceinline__ void up2(u64 v, float& a, float& b) {
    asm("mov.b64 {%0,%1},%2;" : "=f"(a), "=f"(b) : "l"(v));
}
__device__ __forceinline__ u64 f2fma(u64 a, u64 b, u64 c) {
    u64 d; asm("fma.rn.f32x2 %0,%1,%2,%3;" : "=l"(d) : "l"(a), "l"(b), "l"(c)); return d;
}
__device__ __forceinline__ u64 add2(u64 a, u64 b) {
    u64 d; asm("add.rn.f32x2 %0,%1,%2;" : "=l"(d) : "l"(a), "l"(b)); return d;
}
__device__ __forceinline__ u64 relu2(u64 v) {
    u64 r;
    asm("{\n\t.reg .f32 l,h;\n\t"
        "mov.b64 {l,h}, %1;\n\t"
        "max.f32 l, l, 0f00000000;\n\t"
        "max.f32 h, h, 0f00000000;\n\t"
        "mov.b64 %0, {l,h};\n\t}"
        : "=l"(r) : "l"(v));
    return r;
}
__device__ __forceinline__ float tanh_ap(float x) {
    float r; asm("tanh.approx.f32 %0,%1;" : "=f"(r) : "f"(x)); return r;
}
__device__ __forceinline__ float sigm(float x) { return 1.f / (1.f + __expf(-x)); }

// ---------------- staged MLP mean-pool reduction --------------------------
// R12's proven phase at 640 threads (20 warps/SM = 5 warps/SMSP, reg cap 102).
// group of 16 threads (tid&15) -> 4 outputs each (64 total); row-slice =
// tid>>4 (0..39); f32x2 lanes = (rowA, rowB); shared TRANSPOSED sht[k][row]
// so the lane pair is one natural broadcast LDS.64.
#define NTH   640
#define NSL   40                // row slices (NTH/16)
#define RPS   1280              // rows per stage = 2*NTH
#define NIT   16                // compute iterations (RPS/2/NSL)
#define KPAD  1288              // padded float stride (even)

template<int INF>
__device__ __forceinline__ void phase(const float* __restrict__ X,
                                      const float* __restrict__ W,
                                      const float* __restrict__ bias,
                                      int nrows, float* __restrict__ partial,
                                      int nb, int b,
                                      float* __restrict__ sht,  // INF*KPAD floats
                                      float* __restrict__ red)  // NSL*64 floats
{
    const int tid = threadIdx.x;
    const int j0 = (tid & 15) * 4;
    const int rpb = tid >> 4;          // row-slice 0..39

    u64 w2[INF * 4];
    u64 b2[4];
#pragma unroll
    for (int k = 0; k < INF; k++)
#pragma unroll
        for (int jj = 0; jj < 4; jj++) {
            float w = W[k * 64 + j0 + jj];
            w2[k * 4 + jj] = pk2(w, w);
        }
#pragma unroll
    for (int jj = 0; jj < 4; jj++) {
        float bb = bias[j0 + jj];
        b2[jj] = pk2(bb, bb);
    }

    u64 acc[4] = {0ull, 0ull, 0ull, 0ull};

    const int nstages = (nrows + RPS - 1) / RPS;
    float rg[2][INF];

    // prefetch first stage
    if (b < nstages) {
        const int r0 = b * RPS;
#pragma unroll
        for (int t2 = 0; t2 < 2; t2++) {
            const int gr = r0 + tid + t2 * NTH;
            if (gr < nrows) {
#pragma unroll
                for (int k = 0; k < INF; k++) rg[t2][k] = X[gr * INF + k];
            } else {
#pragma unroll
                for (int k = 0; k < INF; k++) rg[t2][k] = 0.f;
            }
        }
    }

    for (int s = b; s < nstages; s += nb) {
        __syncthreads();
#pragma unroll
        for (int t2 = 0; t2 < 2; t2++) {
            const int j = tid + t2 * NTH;
#pragma unroll
            for (int k = 0; k < INF; k++) sht[k * KPAD + j] = rg[t2][k];
        }
        __syncthreads();

        // prefetch next stage (overlaps compute)
        const int sn = s + nb;
        if (sn < nstages) {
            const int r0 = sn * RPS;
#pragma unroll
            for (int t2 = 0; t2 < 2; t2++) {
                const int gr = r0 + tid + t2 * NTH;
                if (gr < nrows) {
#pragma unroll
                    for (int k = 0; k < INF; k++) rg[t2][k] = X[gr * INF + k];
                } else {
#pragma unroll
                    for (int k = 0; k < INF; k++) rg[t2][k] = 0.f;
                }
            }
        }

        const int rows = min(RPS, nrows - s * RPS);
        if (rows == RPS) {
#pragma unroll 4
            for (int it = 0; it < NIT; ++it) {      // 16 iters x 40 slices = 640 rp
                const int rp = it * NSL + rpb;
                u64 x2[INF];
#pragma unroll
                for (int k = 0; k < INF; k++)
                    x2[k] = ((const u64*)(sht + k * KPAD))[rp];
#pragma unroll
                for (int jj = 0; jj < 4; jj++) {
                    u64 y = b2[jj];
#pragma unroll
                    for (int k = 0; k < INF; k++)
                        y = f2fma(x2[k], w2[k * 4 + jj], y);
                    acc[jj] = add2(relu2(y), acc[jj]);
                }
            }
        } else {
#pragma unroll 4
            for (int it = 0; it < NIT; ++it) {
                const int rp = it * NSL + rpb;
                const float m0 = (2 * rp < rows) ? 1.f : 0.f;
                const float m1 = (2 * rp + 1 < rows) ? 1.f : 0.f;
                const u64 mask = pk2(m0, m1);
                u64 x2[INF];
#pragma unroll
                for (int k = 0; k < INF; k++)
                    x2[k] = ((const u64*)(sht + k * KPAD))[rp];
#pragma unroll
                for (int jj = 0; jj < 4; jj++) {
                    u64 y = b2[jj];
#pragma unroll
                    for (int k = 0; k < INF; k++)
                        y = f2fma(x2[k], w2[k * 4 + jj], y);
                    acc[jj] = f2fma(relu2(y), mask, acc[jj]);
                }
            }
        }
    }

    // deterministic cross-thread reduce: red[slice*64 + j]
    __syncthreads();
    {
        float4 v;
        float a, bb;
        up2(acc[0], a, bb); v.x = a + bb;
        up2(acc[1], a, bb); v.y = a + bb;
        up2(acc[2], a, bb); v.z = a + bb;
        up2(acc[3], a, bb); v.w = a + bb;
        ((float4*)red)[tid] = v;    // tid*4 == slice*64 + j0
    }
    __syncthreads();
    if (tid < 64) {
        float s = 0.f;
#pragma unroll 8
        for (int rp = 0; rp < NSL; rp++) s += red[rp * 64 + tid];
        partial[tid] = s;
    }
    __syncthreads();
}

// ---------------- kernel 1: LSTM (block 0) + node/edge reduce -------------
__global__ void __launch_bounds__(NTH, 1) k1(
    const float* __restrict__ node, const float* __restrict__ edge,
    const float* __restrict__ hist, int Nn, int Ne, int T,
    const float* __restrict__ nodeW, const float* __restrict__ nodeb,
    const float* __restrict__ edgeW, const float* __restrict__ edgeb,
    const float* __restrict__ Wih, const float* __restrict__ Whh,
    const float* __restrict__ bih, const float* __restrict__ bhh)
{
    __shared__ __align__(16) float sht[5 * KPAD];   // 25760 B
    __shared__ __align__(16) float red[NSL * 64];   // 10240 B
    __shared__ float sh_hist[608];
    __shared__ float sh_g[256];
    __shared__ __align__(8) float sh_h[64];

    const int tid = threadIdx.x;

    if (blockIdx.x == 0) {
        // ------- LSTM: 256 gate threads (of 640), R2-proven ---------------
        u64 w2[32];
        float wi0 = 0.f, wi1 = 0.f, wi2 = 0.f, bsum = 0.f;
        if (tid < 256) {
            const float2* wr = (const float2*)(Whh + tid * 64);
#pragma unroll
            for (int k = 0; k < 32; k++) { float2 p = wr[k]; w2[k] = pk2(p.x, p.y); }
            wi0 = Wih[tid * 3]; wi1 = Wih[tid * 3 + 1]; wi2 = Wih[tid * 3 + 2];
            bsum = bih[tid] + bhh[tid];
        }
        const bool hsh = (T * 3 <= 608);
        for (int i = tid; i < T * 3 && i < 608; i += NTH) sh_hist[i] = hist[i];
        if (tid < 64) sh_h[tid] = 0.f;
        float c = 0.f;
        __syncthreads();

        const bool is_tanh_gate = (tid >= 128 && tid < 192);
        for (int t = 0; t < T; t++) {
            if (tid < 256) {
                const float* xp = hsh ? (sh_hist + t * 3) : (hist + t * 3);
                float pre = fmaf(wi0, xp[0], fmaf(wi1, xp[1], fmaf(wi2, xp[2], bsum)));
                const u64* hp = (const u64*)sh_h;
                u64 a0 = 0, a1 = 0, a2 = 0, a3 = 0;
#pragma unroll
                for (int k = 0; k < 32; k += 4) {
                    a0 = f2fma(w2[k],     hp[k],     a0);
                    a1 = f2fma(w2[k + 1], hp[k + 1], a1);
                    a2 = f2fma(w2[k + 2], hp[k + 2], a2);
                    a3 = f2fma(w2[k + 3], hp[k + 3], a3);
                }
                float s0, s1, s2, s3, s4, s5, s6, s7;
                up2(a0, s0, s1); up2(a1, s2, s3); up2(a2, s4, s5); up2(a3, s6, s7);
                const float z = pre + ((s0 + s1) + (s2 + s3)) + ((s4 + s5) + (s6 + s7));
                sh_g[tid] = is_tanh_gate ? tanh_ap(z) : sigm(z);
            }
            __syncthreads();
            if (tid < 64) {
                const float ig = sh_g[tid], fg = sh_g[64 + tid];
                const float gg = sh_g[128 + tid], og = sh_g[192 + tid];
                c = fmaf(fg, c, ig * gg);
                sh_h[tid] = og * tanh_ap(c);
            }
            __syncthreads();
        }
        if (tid < 64) g_zhist[tid] = sh_h[tid];
    } else {
        const int b = blockIdx.x - 1;
        const int nb = gridDim.x - 1;
        phase<2>(node, nodeW, nodeb, Nn, g_part_node[b], nb, b, sht, red);
        phase<5>(edge, edgeW, edgeb, Ne, g_part_edge[b], nb, b, sht, red);
    }
}

// ---------------- kernel 2: finalize ctx + precompute base/a/b/w2 ---------
#define NB 147

__global__ void __launch_bounds__(512) k2(int Nn, int Ne,
                   const float* __restrict__ W1, const float* __restrict__ b1,
                   const float* __restrict__ W2f)
{
    __shared__ float ctx[192];
    __shared__ float t1[512], t2[512];
    const int tid = threadIdx.x;
    const int c = tid >> 6, j = tid & 63;   // 8 groups of 64

    float se = 0.f, sn = 0.f;
#pragma unroll
    for (int i = 0; i < 19; i++) {          // ceil(147/8)=19, guarded
        const int b = c + i * 8;
        if (b < NB) {
            se += g_part_edge[b][j];
            sn += g_part_node[b][j];
        }
    }
    t1[tid] = se; t2[tid] = sn;
    __syncthreads();
    if (tid < 64) {
        float e = 0.f, n = 0.f;
#pragma unroll
        for (int g = 0; g < 8; g++) { e += t1[g * 64 + tid]; n += t2[g * 64 + tid]; }
        ctx[tid]       = n * (1.f / (float)Nn);
        ctx[64 + tid]  = e * (1.f / (float)Ne);
        ctx[128 + tid] = g_zhist[tid];
    }
    __syncthreads();
    float p = 0.f;
    const int i0 = c * 24;
#pragma unroll
    for (int i = 0; i < 24; i++) p = fmaf(ctx[i0 + i], W1[(i0 + i) * 64 + j], p);
    __syncthreads();
    t1[tid] = p;
    __syncthreads();
    if (tid < 64) {
        float s = b1[tid];
#pragma unroll
        for (int g = 0; g < 8; g++) s += t1[g * 64 + tid];
        g_base[tid] = s;
        g_av[tid]   = W1[192 * 64 + tid];
        g_bv[tid]   = W1[193 * 64 + tid];
        g_w2v[tid]  = W2f[tid];
    }
}

// ---------------- kernel 3: candidate scoring (ILP=8, measured-best) ------
__global__ void __launch_bounds__(256) k3(const int* __restrict__ cand, int P,
                                          const int* __restrict__ Np,
                                          const float* __restrict__ fb2,
                                          float* __restrict__ out)
{
    __shared__ __align__(16) u64 s4[128];   // [jp]{base2, a2, b2, w22}
    const int tid = threadIdx.x;
    if (tid < 32) {
        s4[tid * 4 + 0] = pk2(g_base[2 * tid], g_base[2 * tid + 1]);
        s4[tid * 4 + 1] = pk2(g_av[2 * tid],   g_av[2 * tid + 1]);
        s4[tid * 4 + 2] = pk2(g_bv[2 * tid],   g_bv[2 * tid + 1]);
        s4[tid * 4 + 3] = pk2(g_w2v[2 * tid],  g_w2v[2 * tid + 1]);
    }
    const float invd = 1.f / ((float)(*Np) - 1.f + 1e-9f);
    const float bias2 = fb2[0];
    __syncthreads();

    const int p0 = blockIdx.x * 2048 + tid;
    u64 cx2[8], cy2[8];
#pragma unroll
    for (int i = 0; i < 8; i++) {
        const int p = p0 + i * 256;
        float cx = 0.f, cy = 0.f;
        if (p < P) {
            const int2 cp = ((const int2*)cand)[p];
            cx = (float)cp.x * invd;
            cy = (float)cp.y * invd;
        }
        cx2[i] = pk2(cx, cx);
        cy2[i] = pk2(cy, cy);
    }

    u64 acc[8] = {0, 0, 0, 0, 0, 0, 0, 0};
#pragma unroll 8
    for (int jp = 0; jp < 32; jp++) {
        const u64 bb = s4[jp * 4 + 0];
        const u64 aa = s4[jp * 4 + 1];
        const u64 bv = s4[jp * 4 + 2];
        const u64 ww = s4[jp * 4 + 3];
#pragma unroll
        for (int i = 0; i < 8; i++) {
            u64 tt = f2fma(cx2[i], aa, bb);
            tt = f2fma(cy2[i], bv, tt);
            acc[i] = f2fma(relu2(tt), ww, acc[i]);
        }
    }
#pragma unroll
    for (int i = 0; i < 8; i++) {
        const int p = p0 + i * 256;
        if (p < P) {
            float l, h; up2(acc[i], l, h);
            out[p] = l + h + bias2;
        }
    }
}

// ---------------- launch ---------------------------------------------------
extern "C" void kernel_launch(void* const* d_in, const int* in_sizes, int n_in,
                              void* d_out, int out_size)
{
    const float* node  = (const float*)d_in[0];
    const float* edge  = (const float*)d_in[1];
    const float* hist  = (const float*)d_in[2];
    const int*   cand  = (const int*)d_in[3];
    const int*   Np    = (const int*)d_in[4];
    const float* nodeW = (const float*)d_in[5];
    const float* nodeb = (const float*)d_in[6];
    const float* edgeW = (const float*)d_in[7];
    const float* edgeb = (const float*)d_in[8];
    const float* Wih   = (const float*)d_in[9];
    const float* Whh   = (const float*)d_in[10];
    const float* bih   = (const float*)d_in[11];
    const float* bhh   = (const float*)d_in[12];
    const float* fW1   = (const float*)d_in[13];
    const float* fb1   = (const float*)d_in[14];
    const float* fW2   = (const float*)d_in[15];
    const float* fb2   = (const float*)d_in[16];

    const int Nn = in_sizes[0] / 2;
    const int Ne = in_sizes[1] / 5;
    const int T  = in_sizes[2] / 3;
    const int P  = in_sizes[3] / 2;

    const int GRID1 = NB + 1;   // block 0 = LSTM, 147 phase blocks
    k1<<<GRID1, NTH>>>(node, edge, hist, Nn, Ne, T,
                       nodeW, nodeb, edgeW, edgeb, Wih, Whh, bih, bhh);
    k2<<<1, 512>>>(Nn, Ne, fW1, fb1, fW2);
    const int g3 = (P + 2047) / 2048;
    k3<<<g3, 256>>>(cand, P, Np, fb2, (float*)d_out);
}

// round 17
// speedup vs baseline: 1.3061x; 1.0533x over previous
#include <cuda_runtime.h>
#include <cstdint>

typedef unsigned long long u64;

// ---------------- device scratch (no allocations allowed) ----------------
__device__ float g_part_edge[160][64];
__device__ float g_part_node[160][64];
__device__ float g_zhist[64];
__device__ float g_base[64];
__device__ float g_av[64];
__device__ float g_bv[64];
__device__ float g_w2v[64];

// ---------------- f32x2 packed helpers ------------------------------------
__device__ __forceinline__ u64 pk2(float a, float b) {
    u64 r; asm("mov.b64 %0,{%1,%2};" : "=l"(r) : "f"(a), "f"(b)); return r;
}
__device__ __forceinline__ void up2(u64 v, float& a, float& b) {
    asm("mov.b64 {%0,%1},%2;" : "=f"(a), "=f"(b) : "l"(v));
}
__device__ __forceinline__ u64 f2fma(u64 a, u64 b, u64 c) {
    u64 d; asm("fma.rn.f32x2 %0,%1,%2,%3;" : "=l"(d) : "l"(a), "l"(b), "l"(c)); return d;
}
__device__ __forceinline__ u64 add2(u64 a, u64 b) {
    u64 d; asm("add.rn.f32x2 %0,%1,%2;" : "=l"(d) : "l"(a), "l"(b)); return d;
}
__device__ __forceinline__ u64 relu2(u64 v) {
    u64 r;
    asm("{\n\t.reg .f32 l,h;\n\t"
        "mov.b64 {l,h}, %1;\n\t"
        "max.f32 l, l, 0f00000000;\n\t"
        "max.f32 h, h, 0f00000000;\n\t"
        "mov.b64 %0, {l,h};\n\t}"
        : "=l"(r) : "l"(v));
    return r;
}
__device__ __forceinline__ float tanh_ap(float x) {
    float r; asm("tanh.approx.f32 %0,%1;" : "=f"(r) : "f"(x)); return r;
}
__device__ __forceinline__ float sigm(float x) { return 1.f / (1.f + __expf(-x)); }

// ---------------- staged MLP mean-pool reduction --------------------------
// R12's proven compute loop (512 thr, 16 slices x 4 outputs, transposed
// shared, broadcast LDS.64) with COALESCED float2 staging: linear loads,
// scatter to sht[k][row] via mod/div (ALU pipe). One variable changed vs R12.
#define NTH   512
#define RPS   1024
#define KPAD  1032

template<int INF>
__device__ __forceinline__ void phase(const float* __restrict__ X,
                                      const float* __restrict__ W,
                                      const float* __restrict__ bias,
                                      int nrows, float* __restrict__ partial,
                                      int nb, int b,
                                      float* __restrict__ sht,  // INF*KPAD floats
                                      float* __restrict__ red)  // 2048 floats
{
    const int tid = threadIdx.x;
    const int j0 = (tid & 15) * 4;
    const int rpb = tid >> 4;          // row-slice 0..31

    u64 w2[INF * 4];
    u64 b2[4];
#pragma unroll
    for (int k = 0; k < INF; k++)
#pragma unroll
        for (int jj = 0; jj < 4; jj++) {
            float w = W[k * 64 + j0 + jj];
            w2[k * 4 + jj] = pk2(w, w);
        }
#pragma unroll
    for (int jj = 0; jj < 4; jj++) {
        float bb = bias[j0 + jj];
        b2[jj] = pk2(bb, bb);
    }

    u64 acc[4] = {0ull, 0ull, 0ull, 0ull};

    const int nstages = (nrows + RPS - 1) / RPS;
    const int nelem = nrows * INF;
    constexpr int NF2 = (RPS * INF) / (2 * NTH);   // float2 per thread: 5 or 2
    float2 rg[NF2];

    // prefetch first stage (coalesced float2)
    if (b < nstages) {
        const int i2 = b * (RPS * INF / 2) + tid;
#pragma unroll
        for (int t = 0; t < NF2; t++) {
            const int e = (i2 + t * NTH) * 2;
            float2 v;
            v.x = (e     < nelem) ? X[e]     : 0.f;
            v.y = (e + 1 < nelem) ? X[e + 1] : 0.f;
            rg[t] = v;
        }
    }

    for (int s = b; s < nstages; s += nb) {
        __syncthreads();
        // scatter into transposed shared: element e -> sht[(e%INF)*KPAD + e/INF]
#pragma unroll
        for (int t = 0; t < NF2; t++) {
            const int e = (tid + t * NTH) * 2;    // local element index
            const int r0 = e / INF, k0 = e - r0 * INF;
            sht[k0 * KPAD + r0] = rg[t].x;
            const int e1 = e + 1;
            const int r1 = e1 / INF, k1 = e1 - r1 * INF;
            sht[k1 * KPAD + r1] = rg[t].y;
        }
        __syncthreads();

        // prefetch next stage (overlaps compute)
        const int sn = s + nb;
        if (sn < nstages) {
            const int i2 = sn * (RPS * INF / 2) + tid;
#pragma unroll
            for (int t = 0; t < NF2; t++) {
                const int e = (i2 + t * NTH) * 2;
                float2 v;
                v.x = (e     < nelem) ? X[e]     : 0.f;
                v.y = (e + 1 < nelem) ? X[e + 1] : 0.f;
                rg[t] = v;
            }
        }

        const int rows = min(RPS, nrows - s * RPS);
        if (rows == RPS) {
#pragma unroll 4
            for (int it = 0; it < RPS / 64; ++it) {
                const int rp = it * 32 + rpb;
                u64 x2[INF];
#pragma unroll
                for (int k = 0; k < INF; k++)
                    x2[k] = ((const u64*)(sht + k * KPAD))[rp];
#pragma unroll
                for (int jj = 0; jj < 4; jj++) {
                    u64 y = b2[jj];
#pragma unroll
                    for (int k = 0; k < INF; k++)
                        y = f2fma(x2[k], w2[k * 4 + jj], y);
                    acc[jj] = add2(relu2(y), acc[jj]);
                }
            }
        } else {
#pragma unroll 4
            for (int it = 0; it < RPS / 64; ++it) {
                const int rp = it * 32 + rpb;
                const float m0 = (2 * rp < rows) ? 1.f : 0.f;
                const float m1 = (2 * rp + 1 < rows) ? 1.f : 0.f;
                const u64 mask = pk2(m0, m1);
                u64 x2[INF];
#pragma unroll
                for (int k = 0; k < INF; k++)
                    x2[k] = ((const u64*)(sht + k * KPAD))[rp];
#pragma unroll
                for (int jj = 0; jj < 4; jj++) {
                    u64 y = b2[jj];
#pragma unroll
                    for (int k = 0; k < INF; k++)
                        y = f2fma(x2[k], w2[k * 4 + jj], y);
                    acc[jj] = f2fma(relu2(y), mask, acc[jj]);
                }
            }
        }
    }

    // deterministic cross-thread reduce
    __syncthreads();
    {
        float4 v;
        float a, bb;
        up2(acc[0], a, bb); v.x = a + bb;
        up2(acc[1], a, bb); v.y = a + bb;
        up2(acc[2], a, bb); v.z = a + bb;
        up2(acc[3], a, bb); v.w = a + bb;
        ((float4*)red)[tid] = v;
    }
    __syncthreads();
    if (tid < 64) {
        float s = 0.f;
#pragma unroll 8
        for (int rp = 0; rp < 32; rp++) s += red[rp * 64 + tid];
        partial[tid] = s;
    }
    __syncthreads();
}

// ---------------- kernel 1: LSTM (block 0) + node/edge reduce -------------
__global__ void __launch_bounds__(NTH, 1) k1(
    const float* __restrict__ node, const float* __restrict__ edge,
    const float* __restrict__ hist, int Nn, int Ne, int T,
    const float* __restrict__ nodeW, const float* __restrict__ nodeb,
    const float* __restrict__ edgeW, const float* __restrict__ edgeb,
    const float* __restrict__ Wih, const float* __restrict__ Whh,
    const float* __restrict__ bih, const float* __restrict__ bhh)
{
    __shared__ __align__(16) float sht[5 * KPAD];
    __shared__ __align__(16) float red[2048];
    __shared__ float sh_hist[608];
    __shared__ float sh_g[256];
    __shared__ __align__(8) float sh_h[64];

    const int tid = threadIdx.x;

    if (blockIdx.x == 0) {
        // ---------------- LSTM: 256 gate threads (of 512), R2-proven ------
        u64 w2[32];
        float wi0 = 0.f, wi1 = 0.f, wi2 = 0.f, bsum = 0.f;
        if (tid < 256) {
            const float2* wr = (const float2*)(Whh + tid * 64);
#pragma unroll
            for (int k = 0; k < 32; k++) { float2 p = wr[k]; w2[k] = pk2(p.x, p.y); }
            wi0 = Wih[tid * 3]; wi1 = Wih[tid * 3 + 1]; wi2 = Wih[tid * 3 + 2];
            bsum = bih[tid] + bhh[tid];
        }
        const bool hsh = (T * 3 <= 608);
        for (int i = tid; i < T * 3 && i < 608; i += NTH) sh_hist[i] = hist[i];
        if (tid < 64) sh_h[tid] = 0.f;
        float c = 0.f;
        __syncthreads();

        const bool is_tanh_gate = (tid >= 128 && tid < 192);
        for (int t = 0; t < T; t++) {
            if (tid < 256) {
                const float* xp = hsh ? (sh_hist + t * 3) : (hist + t * 3);
                float pre = fmaf(wi0, xp[0], fmaf(wi1, xp[1], fmaf(wi2, xp[2], bsum)));
                const u64* hp = (const u64*)sh_h;
                u64 a0 = 0, a1 = 0, a2 = 0, a3 = 0;
#pragma unroll
                for (int k = 0; k < 32; k += 4) {
                    a0 = f2fma(w2[k],     hp[k],     a0);
                    a1 = f2fma(w2[k + 1], hp[k + 1], a1);
                    a2 = f2fma(w2[k + 2], hp[k + 2], a2);
                    a3 = f2fma(w2[k + 3], hp[k + 3], a3);
                }
                float s0, s1, s2, s3, s4, s5, s6, s7;
                up2(a0, s0, s1); up2(a1, s2, s3); up2(a2, s4, s5); up2(a3, s6, s7);
                const float z = pre + ((s0 + s1) + (s2 + s3)) + ((s4 + s5) + (s6 + s7));
                sh_g[tid] = is_tanh_gate ? tanh_ap(z) : sigm(z);
            }
            __syncthreads();
            if (tid < 64) {
                const float ig = sh_g[tid], fg = sh_g[64 + tid];
                const float gg = sh_g[128 + tid], og = sh_g[192 + tid];
                c = fmaf(fg, c, ig * gg);
                sh_h[tid] = og * tanh_ap(c);
            }
            __syncthreads();
        }
        if (tid < 64) g_zhist[tid] = sh_h[tid];
    } else {
        const int b = blockIdx.x - 1;
        const int nb = gridDim.x - 1;
        phase<2>(node, nodeW, nodeb, Nn, g_part_node[b], nb, b, sht, red);
        phase<5>(edge, edgeW, edgeb, Ne, g_part_edge[b], nb, b, sht, red);
    }
}

// ---------------- kernel 2: finalize ctx + precompute base/a/b/w2 ---------
#define NB 147

__global__ void __launch_bounds__(512) k2(int Nn, int Ne,
                   const float* __restrict__ W1, const float* __restrict__ b1,
                   const float* __restrict__ W2f)
{
    __shared__ float ctx[192];
    __shared__ float t1[512], t2[512];
    const int tid = threadIdx.x;
    const int c = tid >> 6, j = tid & 63;   // 8 groups of 64

    float se = 0.f, sn = 0.f;
#pragma unroll
    for (int i = 0; i < 19; i++) {          // ceil(147/8)=19, guarded
        const int b = c + i * 8;
        if (b < NB) {
            se += g_part_edge[b][j];
            sn += g_part_node[b][j];
        }
    }
    t1[tid] = se; t2[tid] = sn;
    __syncthreads();
    if (tid < 64) {
        float e = 0.f, n = 0.f;
#pragma unroll
        for (int g = 0; g < 8; g++) { e += t1[g * 64 + tid]; n += t2[g * 64 + tid]; }
        ctx[tid]       = n * (1.f / (float)Nn);
        ctx[64 + tid]  = e * (1.f / (float)Ne);
        ctx[128 + tid] = g_zhist[tid];
    }
    __syncthreads();
    float p = 0.f;
    const int i0 = c * 24;
#pragma unroll
    for (int i = 0; i < 24; i++) p = fmaf(ctx[i0 + i], W1[(i0 + i) * 64 + j], p);
    __syncthreads();
    t1[tid] = p;
    __syncthreads();
    if (tid < 64) {
        float s = b1[tid];
#pragma unroll
        for (int g = 0; g < 8; g++) s += t1[g * 64 + tid];
        g_base[tid] = s;
        g_av[tid]   = W1[192 * 64 + tid];
        g_bv[tid]   = W1[193 * 64 + tid];
        g_w2v[tid]  = W2f[tid];
    }
}

// ---------------- kernel 3: candidate scoring (ILP=8, measured-best) ------
__global__ void __launch_bounds__(256) k3(const int* __restrict__ cand, int P,
                                          const int* __restrict__ Np,
                                          const float* __restrict__ fb2,
                                          float* __restrict__ out)
{
    __shared__ __align__(16) u64 s4[128];   // [jp]{base2, a2, b2, w22}
    const int tid = threadIdx.x;
    if (tid < 32) {
        s4[tid * 4 + 0] = pk2(g_base[2 * tid], g_base[2 * tid + 1]);
        s4[tid * 4 + 1] = pk2(g_av[2 * tid],   g_av[2 * tid + 1]);
        s4[tid * 4 + 2] = pk2(g_bv[2 * tid],   g_bv[2 * tid + 1]);
        s4[tid * 4 + 3] = pk2(g_w2v[2 * tid],  g_w2v[2 * tid + 1]);
    }
    const float invd = 1.f / ((float)(*Np) - 1.f + 1e-9f);
    const float bias2 = fb2[0];
    __syncthreads();

    const int p0 = blockIdx.x * 2048 + tid;
    u64 cx2[8], cy2[8];
#pragma unroll
    for (int i = 0; i < 8; i++) {
        const int p = p0 + i * 256;
        float cx = 0.f, cy = 0.f;
        if (p < P) {
            const int2 cp = ((const int2*)cand)[p];
            cx = (float)cp.x * invd;
            cy = (float)cp.y * invd;
        }
        cx2[i] = pk2(cx, cx);
        cy2[i] = pk2(cy, cy);
    }

    u64 acc[8] = {0, 0, 0, 0, 0, 0, 0, 0};
#pragma unroll 8
    for (int jp = 0; jp < 32; jp++) {
        const u64 bb = s4[jp * 4 + 0];
        const u64 aa = s4[jp * 4 + 1];
        const u64 bv = s4[jp * 4 + 2];
        const u64 ww = s4[jp * 4 + 3];
#pragma unroll
        for (int i = 0; i < 8; i++) {
            u64 tt = f2fma(cx2[i], aa, bb);
            tt = f2fma(cy2[i], bv, tt);
            acc[i] = f2fma(relu2(tt), ww, acc[i]);
        }
    }
#pragma unroll
    for (int i = 0; i < 8; i++) {
        const int p = p0 + i * 256;
        if (p < P) {
            float l, h; up2(acc[i], l, h);
            out[p] = l + h + bias2;
        }
    }
}

// ---------------- launch ---------------------------------------------------
extern "C" void kernel_launch(void* const* d_in, const int* in_sizes, int n_in,
                              void* d_out, int out_size)
{
    const float* node  = (const float*)d_in[0];
    const float* edge  = (const float*)d_in[1];
    const float* hist  = (const float*)d_in[2];
    const int*   cand  = (const int*)d_in[3];
    const int*   Np    = (const int*)d_in[4];
    const float* nodeW = (const float*)d_in[5];
    const float* nodeb = (const float*)d_in[6];
    const float* edgeW = (const float*)d_in[7];
    const float* edgeb = (const float*)d_in[8];
    const float* Wih   = (const float*)d_in[9];
    const float* Whh   = (const float*)d_in[10];
    const float* bih   = (const float*)d_in[11];
    const float* bhh   = (const float*)d_in[12];
    const float* fW1   = (const float*)d_in[13];
    const float* fb1   = (const float*)d_in[14];
    const float* fW2   = (const float*)d_in[15];
    const float* fb2   = (const float*)d_in[16];

    const int Nn = in_sizes[0] / 2;
    const int Ne = in_sizes[1] / 5;
    const int T  = in_sizes[2] / 3;
    const int P  = in_sizes[3] / 2;

    const int GRID1 = NB + 1;   // block 0 = LSTM, 147 phase blocks
    k1<<<GRID1, NTH>>>(node, edge, hist, Nn, Ne, T,
                       nodeW, nodeb, edgeW, edgeb, Wih, Whh, bih, bhh);
    k2<<<1, 512>>>(Nn, Ne, fW1, fb1, fW2);
    const int g3 = (P + 2047) / 2048;
    k3<<<g3, 256>>>(cand, P, Np, fb2, (float*)d_out);
}